// round 3
// baseline (speedup 1.0000x reference)
#include <cuda_runtime.h>
#include <cuda_bf16.h>
#include <cstdint>

// ----------------------------------------------------------------------------
// VanillaRNN: out = (scan_t h = tanh(xproj_t + h @ W_hh)) @ W_yh + b_y
//   B=128, S=1024, IN=256, HID=1024, OUT=256, fp32
//
// Kernel A: xproj[t][b][n] = x[b][t][:] @ W_hx[:,n] + b_h[n]   (big GEMM)
// Kernel B: persistent cooperative kernel, 128 blocks:
//   - W_hh tile (128k x 64n, 32KB) pinned in SMEM for all 1024 steps
//   - per step: 8-way K-split partial GEMM -> grid barrier -> reduce+tanh -> barrier
//   - tail: out = h_last @ W_yh + b_y
// ----------------------------------------------------------------------------

#define BATCH 128
#define SEQ   1024
#define IND   256
#define HID   1024
#define OUTD  256

#define NBLK  128            // persistent grid size (power of 2 -> wrap-safe barrier)

// Scratch (allowed: __device__ globals)
__device__ float    g_xp[(size_t)SEQ * BATCH * HID];     // 512 MB, layout [t][b][n]
__device__ float    g_h[2][BATCH * HID];                 // ping-pong hidden state
__device__ float    g_part[8][BATCH * HID];              // K-split partials
__device__ unsigned g_bar;                               // monotonic barrier ticket

// ------------------------------- grid barrier -------------------------------
// Monotonic ticket barrier. NBLK is a power of two, so the target rounding is
// exact modulo 2^32 -> no reset needed across graph replays.
__device__ __forceinline__ void grid_sync() {
    __syncthreads();
    if (threadIdx.x == 0) {
        __threadfence();
        unsigned t = atomicAdd(&g_bar, 1u) + 1u;
        unsigned target = (t + (NBLK - 1u)) & ~(unsigned)(NBLK - 1u);
        while ((int)(*(volatile unsigned*)&g_bar - target) < 0) {}
    }
    __syncthreads();
}

// ------------------------------- Kernel A -----------------------------------
// C[m][n] = sum_k X[m][k] * Whx[k][n] + bh[n],  m = b*SEQ + t, M=131072,K=256,N=1024
// Tile 128x128, 256 threads, 8x8 per thread, K-chunk 16.
__global__ __launch_bounds__(256)
void xproj_kernel(const float* __restrict__ X,
                  const float* __restrict__ Whx,
                  const float* __restrict__ bh) {
    __shared__ float sA[16][132];   // transposed: [k][m], pitch 132 (16B-aligned rows)
    __shared__ float sB[16][128];   // [k][n]

    const int tid = threadIdx.x;
    const int m0  = blockIdx.y * 128;
    const int n0  = blockIdx.x * 128;
    const int tx  = tid & 15;       // 16 col groups x 8
    const int ty  = tid >> 4;       // 16 row groups x 8

    float acc[8][8];
#pragma unroll
    for (int r = 0; r < 8; r++)
#pragma unroll
        for (int c = 0; c < 8; c++) acc[r][c] = 0.0f;

    for (int k0 = 0; k0 < IND; k0 += 16) {
        // A: 128 rows x 16 k = 512 float4, 2 per thread; store transposed
#pragma unroll
        for (int i = 0; i < 2; i++) {
            int j  = tid + i * 256;
            int r  = j >> 2;
            int kq = j & 3;
            float4 v = *(const float4*)(X + (size_t)(m0 + r) * IND + k0 + kq * 4);
            sA[kq * 4 + 0][r] = v.x;
            sA[kq * 4 + 1][r] = v.y;
            sA[kq * 4 + 2][r] = v.z;
            sA[kq * 4 + 3][r] = v.w;
        }
        // B: 16 k x 128 n = 512 float4, 2 per thread
#pragma unroll
        for (int i = 0; i < 2; i++) {
            int j  = tid + i * 256;
            int kr = j >> 5;
            int nq = j & 31;
            *(float4*)&sB[kr][nq * 4] =
                *(const float4*)(Whx + (size_t)(k0 + kr) * HID + n0 + nq * 4);
        }
        __syncthreads();
#pragma unroll
        for (int kk = 0; kk < 16; kk++) {
            float a[8], b[8];
            *(float4*)&a[0] = *(const float4*)&sA[kk][ty * 8];
            *(float4*)&a[4] = *(const float4*)&sA[kk][ty * 8 + 4];
            *(float4*)&b[0] = *(const float4*)&sB[kk][tx * 8];
            *(float4*)&b[4] = *(const float4*)&sB[kk][tx * 8 + 4];
#pragma unroll
            for (int r = 0; r < 8; r++)
#pragma unroll
                for (int c = 0; c < 8; c++) acc[r][c] += a[r] * b[c];
        }
        __syncthreads();
    }

    // epilogue: add bias, scatter to [t][b][n]
    float bias[8];
    *(float4*)&bias[0] = *(const float4*)(bh + n0 + tx * 8);
    *(float4*)&bias[4] = *(const float4*)(bh + n0 + tx * 8 + 4);
#pragma unroll
    for (int r = 0; r < 8; r++) {
        int m = m0 + ty * 8 + r;
        int b = m >> 10;        // batch
        int t = m & 1023;       // timestep
        float* dst = g_xp + (size_t)t * (BATCH * HID) + (size_t)b * HID + n0 + tx * 8;
        float4 v0, v1;
        v0.x = acc[r][0] + bias[0]; v0.y = acc[r][1] + bias[1];
        v0.z = acc[r][2] + bias[2]; v0.w = acc[r][3] + bias[3];
        v1.x = acc[r][4] + bias[4]; v1.y = acc[r][5] + bias[5];
        v1.z = acc[r][6] + bias[6]; v1.w = acc[r][7] + bias[7];
        *(float4*)dst       = v0;
        *(float4*)(dst + 4) = v1;
    }
}

// ------------------------------- Kernel B -----------------------------------
// Persistent recurrence. 128 blocks x 256 threads.
// Block bid: nt = bid & 15 -> cols [nt*64, +64);  ks = bid >> 4 -> k in [ks*128, +128)
__global__ __launch_bounds__(256, 1)
void rnn_kernel(const float* __restrict__ Whh,
                const float* __restrict__ Wyh,
                const float* __restrict__ by,
                float* __restrict__ out) {
    __shared__ float sW[128 * 64];   // W_hh tile [k][n], 32 KB, resident all steps
    __shared__ float sH[16][132];    // h chunk, transposed [k][b]

    const int tid = threadIdx.x;
    const int bid = blockIdx.x;
    const int nt  = bid & 15;
    const int ks  = bid >> 4;
    const int n0  = nt * 64;
    const int k0  = ks * 128;
    const int tx  = tid & 15;        // 16 col groups x 4
    const int ty  = tid >> 4;        // 16 batch groups x 8

    // Load this block's W_hh tile once (2048 float4, 8 per thread)
#pragma unroll
    for (int i = 0; i < 8; i++) {
        int j  = tid + i * 256;
        int k  = j >> 4;
        int nq = j & 15;
        *(float4*)&sW[k * 64 + nq * 4] =
            *(const float4*)(Whh + (size_t)(k0 + k) * HID + n0 + nq * 4);
    }

    // step 0: h = tanh(xproj[0])   (h0 = 0)
    {
        int idx = bid * 1024 + tid * 4;
        float4 v = *(const float4*)(g_xp + idx);
        float4 r;
        r.x = tanhf(v.x); r.y = tanhf(v.y); r.z = tanhf(v.z); r.w = tanhf(v.w);
        __stcg((float4*)(g_h[0] + idx), r);
    }
    grid_sync();

    int cur = 0;
    for (int t = 1; t < SEQ; t++) {
        const float* h = g_h[cur];

        // ---- phase 1: partial[ks][b][n] = sum_{k in range} h[b][k] * W[k][n]
        float acc[8][4];
#pragma unroll
        for (int r = 0; r < 8; r++)
#pragma unroll
            for (int c = 0; c < 4; c++) acc[r][c] = 0.0f;

        for (int c = 0; c < 8; c++) {   // 8 chunks of 16 k
            // stage h[0:128][k0+c*16 .. +16] transposed; 512 float4, 2/thread
#pragma unroll
            for (int i = 0; i < 2; i++) {
                int j  = tid + i * 256;
                int b  = j >> 2;
                int kq = j & 3;
                float4 v = __ldcg((const float4*)(h + b * HID + k0 + c * 16 + kq * 4));
                sH[kq * 4 + 0][b] = v.x;
                sH[kq * 4 + 1][b] = v.y;
                sH[kq * 4 + 2][b] = v.z;
                sH[kq * 4 + 3][b] = v.w;
            }
            __syncthreads();
#pragma unroll
            for (int kk = 0; kk < 16; kk++) {
                float hv0[4], hv1[4], wv[4];
                *(float4*)hv0 = *(const float4*)&sH[kk][ty * 8];
                *(float4*)hv1 = *(const float4*)&sH[kk][ty * 8 + 4];
                *(float4*)wv  = *(const float4*)&sW[(c * 16 + kk) * 64 + tx * 4];
#pragma unroll
                for (int cc = 0; cc < 4; cc++) {
                    acc[0][cc] += hv0[0] * wv[cc];
                    acc[1][cc] += hv0[1] * wv[cc];
                    acc[2][cc] += hv0[2] * wv[cc];
                    acc[3][cc] += hv0[3] * wv[cc];
                    acc[4][cc] += hv1[0] * wv[cc];
                    acc[5][cc] += hv1[1] * wv[cc];
                    acc[6][cc] += hv1[2] * wv[cc];
                    acc[7][cc] += hv1[3] * wv[cc];
                }
            }
            __syncthreads();
        }
        // write partials
        float* p = g_part[ks];
#pragma unroll
        for (int r = 0; r < 8; r++) {
            float4 v;
            v.x = acc[r][0]; v.y = acc[r][1]; v.z = acc[r][2]; v.w = acc[r][3];
            __stcg((float4*)(p + (ty * 8 + r) * HID + n0 + tx * 4), v);
        }
        grid_sync();

        // ---- phase 2: h_next = tanh(xproj[t] + sum_ks partial[ks])
        const int nxt = cur ^ 1;
        {
            int idx = bid * 1024 + tid * 4;
            float4 v = *(const float4*)(g_xp + (size_t)t * (BATCH * HID) + idx);
#pragma unroll
            for (int s = 0; s < 8; s++) {
                float4 pv = __ldcg((const float4*)(g_part[s] + idx));
                v.x += pv.x; v.y += pv.y; v.z += pv.z; v.w += pv.w;
            }
            float4 r;
            r.x = tanhf(v.x); r.y = tanhf(v.y); r.z = tanhf(v.z); r.w = tanhf(v.w);
            __stcg((float4*)(g_h[nxt] + idx), r);
        }
        grid_sync();
        cur = nxt;
    }

    // ---- tail: out[b][o] = h_last[b][:] @ W_yh[:,o] + b_y[o]
    // block = batch row, thread = output column
    {
        float* hs = &sH[0][0];   // reuse (needs 4 KB, sH is 8.25 KB)
        const float* hrow = g_h[cur] + bid * HID;
#pragma unroll
        for (int i = 0; i < 4; i++)
            hs[tid + i * 256] = __ldcg(hrow + tid + i * 256);
        __syncthreads();

        float a0 = by[tid], a1 = 0.0f, a2 = 0.0f, a3 = 0.0f;
        for (int k = 0; k < HID; k += 4) {
            a0 += hs[k + 0] * __ldg(Wyh + (size_t)(k + 0) * OUTD + tid);
            a1 += hs[k + 1] * __ldg(Wyh + (size_t)(k + 1) * OUTD + tid);
            a2 += hs[k + 2] * __ldg(Wyh + (size_t)(k + 2) * OUTD + tid);
            a3 += hs[k + 3] * __ldg(Wyh + (size_t)(k + 3) * OUTD + tid);
        }
        out[bid * OUTD + tid] = (a0 + a1) + (a2 + a3);
    }
}

// ------------------------------- launch --------------------------------------
extern "C" void kernel_launch(void* const* d_in, const int* in_sizes, int n_in,
                              void* d_out, int out_size) {
    const float* x   = (const float*)d_in[0];   // [128,1024,256]
    const float* Whx = (const float*)d_in[1];   // [256,1024]
    const float* Whh = (const float*)d_in[2];   // [1024,1024]
    const float* bh  = (const float*)d_in[3];   // [1024]
    const float* Wyh = (const float*)d_in[4];   // [1024,256]
    const float* by  = (const float*)d_in[5];   // [256]
    float* out = (float*)d_out;                 // [128,256]

    dim3 gridA(HID / 128, (BATCH * SEQ) / 128); // (8, 1024)
    xproj_kernel<<<gridA, 256>>>(x, Whx, bh);
    rnn_kernel<<<NBLK, 256>>>(Whh, Wyh, by, out);
}

// round 7
// speedup vs baseline: 1.2354x; 1.2354x over previous
#include <cuda_runtime.h>
#include <cstdint>

// ----------------------------------------------------------------------------
// VanillaRNN: out = (scan_t h = tanh(xproj_t + h @ W_hh)) @ W_yh + b_y
//   B=128, S=1024, IN=256, HID=1024, OUT=256, fp32
//
// Kernel A: xproj[t][b][n] = x[b][t][:] @ W_hx[:,n] + b_h[n]   (fp32 GEMM)
// Kernel B: persistent cooperative kernel, 128 blocks x 256 threads:
//   per-CTA tile: ks = k-range of 128, nt = n-range of 64
//   W_hh tile -> tf32 hi/lo REGISTER-resident for all 1024 steps
//   per step: stage h (fp32, SMEM) -> mma.sync m16n8k8 tf32, 3-term Markidis
//             -> partials -> grid barrier -> reduce+tanh -> barrier
// (tcgen05 unavailable: harness compiles at compute_100, not sm_100a.
//  mma.sync tf32 is sm_80+ and needs no arch suffix.)
// ----------------------------------------------------------------------------

#define BATCH 128
#define SEQ   1024
#define IND   256
#define HID   1024
#define OUTD  256
#define NBLK  128

#define SH_PITCH 132
#define RNN_SMEM (128 * SH_PITCH * 4)   // 67584 B

// Scratch (__device__ globals only)
__device__ float    g_xp[(size_t)SEQ * BATCH * HID];     // 512 MB, [t][b][n]
__device__ float    g_h[2][BATCH * HID];                 // ping-pong hidden state
__device__ float    g_part[8][BATCH * HID];              // K-split partials
__device__ unsigned g_bar;                               // monotonic barrier ticket

// ------------------------------- grid barrier -------------------------------
__device__ __forceinline__ void grid_sync() {
    __syncthreads();
    if (threadIdx.x == 0) {
        __threadfence();
        unsigned t = atomicAdd(&g_bar, 1u) + 1u;
        unsigned target = (t + (NBLK - 1u)) & ~(unsigned)(NBLK - 1u);
        while ((int)(*(volatile unsigned*)&g_bar - target) < 0) {}
    }
    __syncthreads();
}

// ------------------------------- helpers ------------------------------------
__device__ __forceinline__ uint32_t f2tf(float x) {     // round-to-nearest tf32 bits
    uint32_t r;
    asm("cvt.rna.tf32.f32 %0, %1;" : "=r"(r) : "f"(x));
    return r;
}

// D(16x8) += A(16x8,row) * B(8x8,col), tf32 inputs / f32 accum
__device__ __forceinline__ void mma8(float* c, const uint32_t* a,
                                     uint32_t b0, uint32_t b1) {
    asm volatile(
        "mma.sync.aligned.m16n8k8.row.col.f32.tf32.tf32.f32 "
        "{%0,%1,%2,%3}, {%4,%5,%6,%7}, {%8,%9}, {%0,%1,%2,%3};"
        : "+f"(c[0]), "+f"(c[1]), "+f"(c[2]), "+f"(c[3])
        : "r"(a[0]), "r"(a[1]), "r"(a[2]), "r"(a[3]), "r"(b0), "r"(b1));
}

// ------------------------------- Kernel A -----------------------------------
__global__ __launch_bounds__(256)
void xproj_kernel(const float* __restrict__ X,
                  const float* __restrict__ Whx,
                  const float* __restrict__ bh) {
    __shared__ float sA[16][132];
    __shared__ float sB[16][128];

    const int tid = threadIdx.x;
    const int m0  = blockIdx.y * 128;
    const int n0  = blockIdx.x * 128;
    const int tx  = tid & 15;
    const int ty  = tid >> 4;

    float acc[8][8];
#pragma unroll
    for (int r = 0; r < 8; r++)
#pragma unroll
        for (int c = 0; c < 8; c++) acc[r][c] = 0.0f;

    for (int k0 = 0; k0 < IND; k0 += 16) {
#pragma unroll
        for (int i = 0; i < 2; i++) {
            int j  = tid + i * 256;
            int r  = j >> 2;
            int kq = j & 3;
            float4 v = *(const float4*)(X + (size_t)(m0 + r) * IND + k0 + kq * 4);
            sA[kq * 4 + 0][r] = v.x;
            sA[kq * 4 + 1][r] = v.y;
            sA[kq * 4 + 2][r] = v.z;
            sA[kq * 4 + 3][r] = v.w;
        }
#pragma unroll
        for (int i = 0; i < 2; i++) {
            int j  = tid + i * 256;
            int kr = j >> 5;
            int nq = j & 31;
            *(float4*)&sB[kr][nq * 4] =
                *(const float4*)(Whx + (size_t)(k0 + kr) * HID + n0 + nq * 4);
        }
        __syncthreads();
#pragma unroll
        for (int kk = 0; kk < 16; kk++) {
            float a[8], b[8];
            *(float4*)&a[0] = *(const float4*)&sA[kk][ty * 8];
            *(float4*)&a[4] = *(const float4*)&sA[kk][ty * 8 + 4];
            *(float4*)&b[0] = *(const float4*)&sB[kk][tx * 8];
            *(float4*)&b[4] = *(const float4*)&sB[kk][tx * 8 + 4];
#pragma unroll
            for (int r = 0; r < 8; r++)
#pragma unroll
                for (int c = 0; c < 8; c++) acc[r][c] += a[r] * b[c];
        }
        __syncthreads();
    }

    float bias[8];
    *(float4*)&bias[0] = *(const float4*)(bh + n0 + tx * 8);
    *(float4*)&bias[4] = *(const float4*)(bh + n0 + tx * 8 + 4);
#pragma unroll
    for (int r = 0; r < 8; r++) {
        int m = m0 + ty * 8 + r;
        int b = m >> 10;
        int t = m & 1023;
        float* dst = g_xp + (size_t)t * (BATCH * HID) + (size_t)b * HID + n0 + tx * 8;
        float4 v0, v1;
        v0.x = acc[r][0] + bias[0]; v0.y = acc[r][1] + bias[1];
        v0.z = acc[r][2] + bias[2]; v0.w = acc[r][3] + bias[3];
        v1.x = acc[r][4] + bias[4]; v1.y = acc[r][5] + bias[5];
        v1.z = acc[r][6] + bias[6]; v1.w = acc[r][7] + bias[7];
        *(float4*)dst       = v0;
        *(float4*)(dst + 4) = v1;
    }
}

// ------------------------------- Kernel B -----------------------------------
// Warp w (0..7): mhalf = w>>2 (rows [mhalf*64, +64)), nq = w&3 (cols [nq*16,+16))
// Lane: g = lane>>2 (0..7), tig = lane&3 (0..3)
// Fragment layout (m16n8k8 tf32, PTX ISA):
//   A: a0(g,tig) a1(g+8,tig) a2(g,tig+4) a3(g+8,tig+4)   [row x k]
//   B: b0(k=tig, n=g) b1(k=tig+4, n=g)
//   C: c0(g,2tig) c1(g,2tig+1) c2(g+8,2tig) c3(g+8,2tig+1)
__global__ __launch_bounds__(256, 1)
void rnn_kernel(const float* __restrict__ Whh,
                const float* __restrict__ Wyh,
                const float* __restrict__ by,
                float* __restrict__ out) {
    extern __shared__ float sH[];   // [128][SH_PITCH]

    const int tid   = threadIdx.x;
    const int bid   = blockIdx.x;
    const int nt    = bid & 15;
    const int ks    = bid >> 4;
    const int n0    = nt * 64;
    const int k0    = ks * 128;
    const int wid   = tid >> 5;
    const int lane  = tid & 31;
    const int g     = lane >> 2;
    const int tig   = lane & 3;
    const int mhalf = wid >> 2;
    const int nq    = wid & 3;

    // ---- preload W_hh tile into registers, tf32 hi/lo (fixed for all steps)
    uint32_t bh0[16][2], bh1[16][2], bl0[16][2], bl1[16][2];
#pragma unroll
    for (int kk = 0; kk < 16; kk++) {
#pragma unroll
        for (int nf = 0; nf < 2; nf++) {
            int ncol = n0 + nq * 16 + nf * 8 + g;
            float w0 = Whh[(size_t)(k0 + kk * 8 + tig)     * HID + ncol];
            float w1 = Whh[(size_t)(k0 + kk * 8 + tig + 4) * HID + ncol];
            bh0[kk][nf] = f2tf(w0);
            bh1[kk][nf] = f2tf(w1);
            bl0[kk][nf] = f2tf(w0 - __uint_as_float(bh0[kk][nf]));
            bl1[kk][nf] = f2tf(w1 - __uint_as_float(bh1[kk][nf]));
        }
    }

    // ---- step 0: h = tanh(xproj[0])   (h0 = 0)
    {
        int idx = bid * 1024 + tid * 4;
        float4 v = *(const float4*)(g_xp + idx);
        float4 r;
        r.x = tanhf(v.x); r.y = tanhf(v.y); r.z = tanhf(v.z); r.w = tanhf(v.w);
        __stcg((float4*)(g_h[0] + idx), r);
    }
    grid_sync();

    int cur = 0;
    for (int t = 1; t < SEQ; t++) {
        const float* h = g_h[cur];

        // ---- stage h[0:128][k0:k0+128] into SMEM (fp32)
#pragma unroll
        for (int r = 0; r < 16; r++) {
            int idx4 = tid + r * 256;
            int m  = idx4 >> 5;
            int kq = (idx4 & 31) * 4;
            float4 v = __ldcg((const float4*)(h + (size_t)m * HID + k0 + kq));
            *(float4*)&sH[m * SH_PITCH + kq] = v;
        }
        __syncthreads();

        // ---- 3-term tf32 MMA: D[m64][n16] per warp
        float c[4][2][4];
#pragma unroll
        for (int mf = 0; mf < 4; mf++)
#pragma unroll
            for (int nf = 0; nf < 2; nf++)
#pragma unroll
                for (int i = 0; i < 4; i++) c[mf][nf][i] = 0.0f;

#pragma unroll
        for (int kk = 0; kk < 16; kk++) {
            const float* base = sH + (mhalf * 64 + g) * SH_PITCH + kk * 8 + tig;
            // load + split all A fragments for this k-step first (better sched)
            uint32_t ah[4][4], al[4][4];
#pragma unroll
            for (int mf = 0; mf < 4; mf++) {
                const float* pa = base + mf * 16 * SH_PITCH;
                float x0 = pa[0];
                float x1 = pa[8 * SH_PITCH];
                float x2 = pa[4];
                float x3 = pa[8 * SH_PITCH + 4];
                ah[mf][0] = f2tf(x0); al[mf][0] = f2tf(x0 - __uint_as_float(ah[mf][0]));
                ah[mf][1] = f2tf(x1); al[mf][1] = f2tf(x1 - __uint_as_float(ah[mf][1]));
                ah[mf][2] = f2tf(x2); al[mf][2] = f2tf(x2 - __uint_as_float(ah[mf][2]));
                ah[mf][3] = f2tf(x3); al[mf][3] = f2tf(x3 - __uint_as_float(ah[mf][3]));
            }
#pragma unroll
            for (int mf = 0; mf < 4; mf++) {
#pragma unroll
                for (int nf = 0; nf < 2; nf++) {
                    mma8(c[mf][nf], ah[mf], bh0[kk][nf], bh1[kk][nf]);  // hi*hi
                    mma8(c[mf][nf], ah[mf], bl0[kk][nf], bl1[kk][nf]);  // hi*loW
                    mma8(c[mf][nf], al[mf], bh0[kk][nf], bh1[kk][nf]);  // loH*hi
                }
            }
        }

        // ---- write partials (32-bit addressing within a partial buffer)
        {
            float* pb = g_part[ks];
            const int cbase = n0 + nq * 16 + tig * 2;
#pragma unroll
            for (int mf = 0; mf < 4; mf++) {
                int r0 = mhalf * 64 + mf * 16 + g;
#pragma unroll
                for (int nf = 0; nf < 2; nf++) {
                    float2 v0 = make_float2(c[mf][nf][0], c[mf][nf][1]);
                    float2 v1 = make_float2(c[mf][nf][2], c[mf][nf][3]);
                    __stcg((float2*)(pb + (r0 << 10) + cbase + nf * 8), v0);
                    __stcg((float2*)(pb + ((r0 + 8) << 10) + cbase + nf * 8), v1);
                }
            }
        }
        grid_sync();

        // ---- reduce 8 partials + xp, tanh, store h_next
        const int nxt = cur ^ 1;
        {
            int idx = bid * 1024 + tid * 4;
            float4 v = *(const float4*)(g_xp + (size_t)t * (BATCH * HID) + idx);
#pragma unroll
            for (int s = 0; s < 8; s++) {
                float4 pv = __ldcg((const float4*)(g_part[s] + idx));
                v.x += pv.x; v.y += pv.y; v.z += pv.z; v.w += pv.w;
            }
            float4 r;
            r.x = tanhf(v.x); r.y = tanhf(v.y); r.z = tanhf(v.z); r.w = tanhf(v.w);
            __stcg((float4*)(g_h[nxt] + idx), r);
        }
        grid_sync();
        cur = nxt;
    }

    // ---- tail: out[b][o] = h_last[b][:] @ W_yh[:,o] + b_y[o]
    {
        float* hs = sH;
        const float* hrow = g_h[cur] + bid * HID;
#pragma unroll
        for (int i = 0; i < 4; i++)
            hs[tid + i * 256] = __ldcg(hrow + tid + i * 256);
        __syncthreads();

        float a0 = by[tid], a1 = 0.0f, a2 = 0.0f, a3 = 0.0f;
        for (int k = 0; k < HID; k += 4) {
            a0 += hs[k + 0] * __ldg(Wyh + (size_t)(k + 0) * OUTD + tid);
            a1 += hs[k + 1] * __ldg(Wyh + (size_t)(k + 1) * OUTD + tid);
            a2 += hs[k + 2] * __ldg(Wyh + (size_t)(k + 2) * OUTD + tid);
            a3 += hs[k + 3] * __ldg(Wyh + (size_t)(k + 3) * OUTD + tid);
        }
        out[bid * OUTD + tid] = (a0 + a1) + (a2 + a3);
    }
}

// ------------------------------- launch --------------------------------------
extern "C" void kernel_launch(void* const* d_in, const int* in_sizes, int n_in,
                              void* d_out, int out_size) {
    const float* x   = (const float*)d_in[0];
    const float* Whx = (const float*)d_in[1];
    const float* Whh = (const float*)d_in[2];
    const float* bh  = (const float*)d_in[3];
    const float* Wyh = (const float*)d_in[4];
    const float* by  = (const float*)d_in[5];
    float* out = (float*)d_out;

    cudaFuncSetAttribute(rnn_kernel,
                         cudaFuncAttributeMaxDynamicSharedMemorySize, RNN_SMEM);

    dim3 gridA(HID / 128, (BATCH * SEQ) / 128);
    xproj_kernel<<<gridA, 256>>>(x, Whx, bh);
    rnn_kernel<<<NBLK, 256, RNN_SMEM>>>(Whh, Wyh, by, out);
}

// round 9
// speedup vs baseline: 1.3207x; 1.0690x over previous
#include <cuda_runtime.h>
#include <cstdint>

// ----------------------------------------------------------------------------
// VanillaRNN: out = (scan_t h = tanh(xproj_t + h @ W_hh)) @ W_yh + b_y
//   B=128, S=1024, IN=256, HID=1024, OUT=256, fp32
//
// Kernel A: xproj[t][b][n] = x[b][t][:] @ W_hx[:,n] + b_h[n]   (fp32 GEMM)
// Kernel B: persistent cooperative kernel, 128 blocks x 256 threads:
//   per-CTA tile: ks = k-range of 128, nt = n-range of 64
//   W_hh tile -> tf32 hi/lo REGISTER-resident for all 1024 steps
//   h hi/lo split computed ONCE per element in the reduce phase (stored as
//   u32 tf32 bits in global); MMA phase stages raw bits -> zero CVT in loop
//   per step: stage h_hi/h_lo (SMEM) -> mma.sync m16n8k8 tf32, 3-term Markidis
//             -> partials -> grid barrier -> reduce+tanh+split -> barrier
// ----------------------------------------------------------------------------

#define BATCH 128
#define SEQ   1024
#define IND   256
#define HID   1024
#define OUTD  256
#define NBLK  128

#define SH_PITCH 132
#define SH_ELEMS (128 * SH_PITCH)            // 16896 u32 per array
#define RNN_SMEM (2 * SH_ELEMS * 4)          // 135168 B (hi + lo tiles)

// Scratch (__device__ globals only)
__device__ float    g_xp[(size_t)SEQ * BATCH * HID];     // 512 MB, [t][b][n]
__device__ float    g_h[2][BATCH * HID];                 // fp32 h (for tail)
__device__ uint32_t g_hhi[2][BATCH * HID];               // tf32 hi bits
__device__ uint32_t g_hlo[2][BATCH * HID];               // tf32 lo bits
__device__ float    g_part[8][BATCH * HID];              // K-split partials
__device__ unsigned g_bar;                               // monotonic barrier ticket

// ------------------------------- grid barrier -------------------------------
__device__ __forceinline__ void grid_sync() {
    __syncthreads();
    if (threadIdx.x == 0) {
        __threadfence();
        unsigned t = atomicAdd(&g_bar, 1u) + 1u;
        unsigned target = (t + (NBLK - 1u)) & ~(unsigned)(NBLK - 1u);
        while ((int)(*(volatile unsigned*)&g_bar - target) < 0) {}
    }
    __syncthreads();
}

// ------------------------------- helpers ------------------------------------
__device__ __forceinline__ uint32_t f2tf(float x) {     // round-to-nearest tf32 bits
    uint32_t r;
    asm("cvt.rna.tf32.f32 %0, %1;" : "=r"(r) : "f"(x));
    return r;
}

// D(16x8) += A(16x8,row) * B(8x8,col), tf32 inputs / f32 accum
__device__ __forceinline__ void mma8(float* c, const uint32_t* a,
                                     uint32_t b0, uint32_t b1) {
    asm volatile(
        "mma.sync.aligned.m16n8k8.row.col.f32.tf32.tf32.f32 "
        "{%0,%1,%2,%3}, {%4,%5,%6,%7}, {%8,%9}, {%0,%1,%2,%3};"
        : "+f"(c[0]), "+f"(c[1]), "+f"(c[2]), "+f"(c[3])
        : "r"(a[0]), "r"(a[1]), "r"(a[2]), "r"(a[3]), "r"(b0), "r"(b1));
}

// tanh + hi/lo split + 3-way store for 4 elements
__device__ __forceinline__ void tanh_split_store(float4 v, float* hp,
                                                 uint32_t* hip, uint32_t* lop) {
    float4 r;
    r.x = tanhf(v.x); r.y = tanhf(v.y); r.z = tanhf(v.z); r.w = tanhf(v.w);
    uint4 hi, lo;
    hi.x = f2tf(r.x); lo.x = f2tf(r.x - __uint_as_float(hi.x));
    hi.y = f2tf(r.y); lo.y = f2tf(r.y - __uint_as_float(hi.y));
    hi.z = f2tf(r.z); lo.z = f2tf(r.z - __uint_as_float(hi.z));
    hi.w = f2tf(r.w); lo.w = f2tf(r.w - __uint_as_float(hi.w));
    __stcg((float4*)hp, r);
    __stcg((uint4*)hip, hi);
    __stcg((uint4*)lop, lo);
}

// ------------------------------- Kernel A -----------------------------------
__global__ __launch_bounds__(256)
void xproj_kernel(const float* __restrict__ X,
                  const float* __restrict__ Whx,
                  const float* __restrict__ bh) {
    __shared__ float sA[16][132];
    __shared__ float sB[16][128];

    const int tid = threadIdx.x;
    const int m0  = blockIdx.y * 128;
    const int n0  = blockIdx.x * 128;
    const int tx  = tid & 15;
    const int ty  = tid >> 4;

    float acc[8][8];
#pragma unroll
    for (int r = 0; r < 8; r++)
#pragma unroll
        for (int c = 0; c < 8; c++) acc[r][c] = 0.0f;

    for (int k0 = 0; k0 < IND; k0 += 16) {
#pragma unroll
        for (int i = 0; i < 2; i++) {
            int j  = tid + i * 256;
            int r  = j >> 2;
            int kq = j & 3;
            float4 v = *(const float4*)(X + (size_t)(m0 + r) * IND + k0 + kq * 4);
            sA[kq * 4 + 0][r] = v.x;
            sA[kq * 4 + 1][r] = v.y;
            sA[kq * 4 + 2][r] = v.z;
            sA[kq * 4 + 3][r] = v.w;
        }
#pragma unroll
        for (int i = 0; i < 2; i++) {
            int j  = tid + i * 256;
            int kr = j >> 5;
            int nq = j & 31;
            *(float4*)&sB[kr][nq * 4] =
                *(const float4*)(Whx + (size_t)(k0 + kr) * HID + n0 + nq * 4);
        }
        __syncthreads();
#pragma unroll
        for (int kk = 0; kk < 16; kk++) {
            float a[8], b[8];
            *(float4*)&a[0] = *(const float4*)&sA[kk][ty * 8];
            *(float4*)&a[4] = *(const float4*)&sA[kk][ty * 8 + 4];
            *(float4*)&b[0] = *(const float4*)&sB[kk][tx * 8];
            *(float4*)&b[4] = *(const float4*)&sB[kk][tx * 8 + 4];
#pragma unroll
            for (int r = 0; r < 8; r++)
#pragma unroll
                for (int c = 0; c < 8; c++) acc[r][c] += a[r] * b[c];
        }
        __syncthreads();
    }

    float bias[8];
    *(float4*)&bias[0] = *(const float4*)(bh + n0 + tx * 8);
    *(float4*)&bias[4] = *(const float4*)(bh + n0 + tx * 8 + 4);
#pragma unroll
    for (int r = 0; r < 8; r++) {
        int m = m0 + ty * 8 + r;
        int b = m >> 10;
        int t = m & 1023;
        float* dst = g_xp + (size_t)t * (BATCH * HID) + (size_t)b * HID + n0 + tx * 8;
        float4 v0, v1;
        v0.x = acc[r][0] + bias[0]; v0.y = acc[r][1] + bias[1];
        v0.z = acc[r][2] + bias[2]; v0.w = acc[r][3] + bias[3];
        v1.x = acc[r][4] + bias[4]; v1.y = acc[r][5] + bias[5];
        v1.z = acc[r][6] + bias[6]; v1.w = acc[r][7] + bias[7];
        *(float4*)dst       = v0;
        *(float4*)(dst + 4) = v1;
    }
}

// ------------------------------- Kernel B -----------------------------------
// Warp w (0..7): mhalf = w>>2 (rows [mhalf*64, +64)), nq = w&3 (cols [nq*16,+16))
// Lane: g = lane>>2 (0..7), tig = lane&3 (0..3)
// Fragment layout (m16n8k8 tf32, PTX ISA):
//   A: a0(g,tig) a1(g+8,tig) a2(g,tig+4) a3(g+8,tig+4)   [row x k]
//   B: b0(k=tig, n=g) b1(k=tig+4, n=g)
//   C: c0(g,2tig) c1(g,2tig+1) c2(g+8,2tig) c3(g+8,2tig+1)
__global__ __launch_bounds__(256, 1)
void rnn_kernel(const float* __restrict__ Whh,
                const float* __restrict__ Wyh,
                const float* __restrict__ by,
                float* __restrict__ out) {
    extern __shared__ uint32_t sMem[];
    uint32_t* sHhi = sMem;                 // [128][SH_PITCH] tf32 hi bits
    uint32_t* sHlo = sMem + SH_ELEMS;      // [128][SH_PITCH] tf32 lo bits

    const int tid   = threadIdx.x;
    const int bid   = blockIdx.x;
    const int nt    = bid & 15;
    const int ks    = bid >> 4;
    const int n0    = nt * 64;
    const int k0    = ks * 128;
    const int wid   = tid >> 5;
    const int lane  = tid & 31;
    const int g     = lane >> 2;
    const int tig   = lane & 3;
    const int mhalf = wid >> 2;
    const int nq    = wid & 3;

    // ---- preload W_hh tile into registers, tf32 hi/lo (fixed for all steps)
    uint32_t bh0[16][2], bh1[16][2], bl0[16][2], bl1[16][2];
#pragma unroll
    for (int kk = 0; kk < 16; kk++) {
#pragma unroll
        for (int nf = 0; nf < 2; nf++) {
            int ncol = n0 + nq * 16 + nf * 8 + g;
            float w0 = Whh[(size_t)(k0 + kk * 8 + tig)     * HID + ncol];
            float w1 = Whh[(size_t)(k0 + kk * 8 + tig + 4) * HID + ncol];
            bh0[kk][nf] = f2tf(w0);
            bh1[kk][nf] = f2tf(w1);
            bl0[kk][nf] = f2tf(w0 - __uint_as_float(bh0[kk][nf]));
            bl1[kk][nf] = f2tf(w1 - __uint_as_float(bh1[kk][nf]));
        }
    }

    // ---- step 0: h = tanh(xproj[0]), emit fp32 + hi/lo   (h0 = 0)
    {
        int idx = bid * 1024 + tid * 4;
        float4 v = *(const float4*)(g_xp + idx);
        tanh_split_store(v, g_h[0] + idx, g_hhi[0] + idx, g_hlo[0] + idx);
    }
    grid_sync();

    int cur = 0;
    for (int t = 1; t < SEQ; t++) {
        const uint32_t* hhi = g_hhi[cur];
        const uint32_t* hlo = g_hlo[cur];

        // ---- stage h_hi/h_lo [0:128][k0:k0+128] into SMEM (raw tf32 bits)
#pragma unroll
        for (int r = 0; r < 16; r++) {
            int idx4 = tid + r * 256;
            int m  = idx4 >> 5;
            int kq = (idx4 & 31) * 4;
            uint4 vh = __ldcg((const uint4*)(hhi + m * HID + k0 + kq));
            uint4 vl = __ldcg((const uint4*)(hlo + m * HID + k0 + kq));
            *(uint4*)&sHhi[m * SH_PITCH + kq] = vh;
            *(uint4*)&sHlo[m * SH_PITCH + kq] = vl;
        }
        __syncthreads();

        // ---- 3-term tf32 MMA: D[m64][n16] per warp (no CVT in loop)
        float c[4][2][4];
#pragma unroll
        for (int mf = 0; mf < 4; mf++)
#pragma unroll
            for (int nf = 0; nf < 2; nf++)
#pragma unroll
                for (int i = 0; i < 4; i++) c[mf][nf][i] = 0.0f;

#pragma unroll
        for (int kk = 0; kk < 16; kk++) {
            const int ob = (mhalf * 64 + g) * SH_PITCH + kk * 8 + tig;
#pragma unroll
            for (int mf = 0; mf < 4; mf++) {
                const int om = ob + mf * 16 * SH_PITCH;
                uint32_t ah[4], al[4];
                ah[0] = sHhi[om];
                ah[1] = sHhi[om + 8 * SH_PITCH];
                ah[2] = sHhi[om + 4];
                ah[3] = sHhi[om + 8 * SH_PITCH + 4];
                al[0] = sHlo[om];
                al[1] = sHlo[om + 8 * SH_PITCH];
                al[2] = sHlo[om + 4];
                al[3] = sHlo[om + 8 * SH_PITCH + 4];
#pragma unroll
                for (int nf = 0; nf < 2; nf++) {
                    mma8(c[mf][nf], ah, bh0[kk][nf], bh1[kk][nf]);  // hi*hi
                    mma8(c[mf][nf], ah, bl0[kk][nf], bl1[kk][nf]);  // hi*loW
                    mma8(c[mf][nf], al, bh0[kk][nf], bh1[kk][nf]);  // loH*hi
                }
            }
        }

        // ---- write partials (32-bit addressing within a partial buffer)
        {
            float* pb = g_part[ks];
            const int cbase = n0 + nq * 16 + tig * 2;
#pragma unroll
            for (int mf = 0; mf < 4; mf++) {
                int r0 = mhalf * 64 + mf * 16 + g;
#pragma unroll
                for (int nf = 0; nf < 2; nf++) {
                    float2 v0 = make_float2(c[mf][nf][0], c[mf][nf][1]);
                    float2 v1 = make_float2(c[mf][nf][2], c[mf][nf][3]);
                    __stcg((float2*)(pb + (r0 << 10) + cbase + nf * 8), v0);
                    __stcg((float2*)(pb + ((r0 + 8) << 10) + cbase + nf * 8), v1);
                }
            }
        }
        grid_sync();

        // ---- reduce 8 partials + xp, tanh, split hi/lo, store h_next
        const int nxt = cur ^ 1;
        {
            int idx = bid * 1024 + tid * 4;
            float4 v = *(const float4*)(g_xp + (size_t)t * (BATCH * HID) + idx);
#pragma unroll
            for (int s = 0; s < 8; s++) {
                float4 pv = __ldcg((const float4*)(g_part[s] + idx));
                v.x += pv.x; v.y += pv.y; v.z += pv.z; v.w += pv.w;
            }
            tanh_split_store(v, g_h[nxt] + idx, g_hhi[nxt] + idx, g_hlo[nxt] + idx);
        }
        grid_sync();
        cur = nxt;
    }

    // ---- tail: out[b][o] = h_last[b][:] @ W_yh[:,o] + b_y[o]
    {
        float* hs = (float*)sMem;
        const float* hrow = g_h[cur] + bid * HID;
#pragma unroll
        for (int i = 0; i < 4; i++)
            hs[tid + i * 256] = __ldcg(hrow + tid + i * 256);
        __syncthreads();

        float a0 = by[tid], a1 = 0.0f, a2 = 0.0f, a3 = 0.0f;
        for (int k = 0; k < HID; k += 4) {
            a0 += hs[k + 0] * __ldg(Wyh + (size_t)(k + 0) * OUTD + tid);
            a1 += hs[k + 1] * __ldg(Wyh + (size_t)(k + 1) * OUTD + tid);
            a2 += hs[k + 2] * __ldg(Wyh + (size_t)(k + 2) * OUTD + tid);
            a3 += hs[k + 3] * __ldg(Wyh + (size_t)(k + 3) * OUTD + tid);
        }
        out[bid * OUTD + tid] = (a0 + a1) + (a2 + a3);
    }
}

// ------------------------------- launch --------------------------------------
extern "C" void kernel_launch(void* const* d_in, const int* in_sizes, int n_in,
                              void* d_out, int out_size) {
    const float* x   = (const float*)d_in[0];
    const float* Whx = (const float*)d_in[1];
    const float* Whh = (const float*)d_in[2];
    const float* bh  = (const float*)d_in[3];
    const float* Wyh = (const float*)d_in[4];
    const float* by  = (const float*)d_in[5];
    float* out = (float*)d_out;

    cudaFuncSetAttribute(rnn_kernel,
                         cudaFuncAttributeMaxDynamicSharedMemorySize, RNN_SMEM);

    dim3 gridA(HID / 128, (BATCH * SEQ) / 128);
    xproj_kernel<<<gridA, 256>>>(x, Whx, bh);
    rnn_kernel<<<NBLK, 256, RNN_SMEM>>>(Whh, Wyh, by, out);
}